// round 5
// baseline (speedup 1.0000x reference)
#include <cuda_runtime.h>
#include <cstdint>

// CTC loss forward, producer/consumer warp-specialized: 2 warps per batch elem.
// B=1024, T=256, C=128, L=32 -> S=65 states. Warp1 (producer) computes log2
// softmax lp pairs per step into a smem ring; warp0 (consumer) runs the alpha
// DP chain. mbarrier ring sync every 8 steps. All math in log2 domain.

#define TN 256
#define CN 128
#define LN 32
#define PADV 127
#define NEGF (-1e30f)
#define LOG2E 1.4426950408889634f
#define NLN2 0.6931471805599453f
#define DSLOT 16      // ring slots (time steps buffered)
#define GRP 8         // steps per sync group
#define NGRP (TN / GRP)
#define SLOTW 36      // floats per slot (32 lane lp + blank lp + pad)

__device__ __forceinline__ float ex2(float x) {
    float r; asm("ex2.approx.f32 %0, %1;" : "=f"(r) : "f"(x)); return r;
}
__device__ __forceinline__ float lg2(float x) {
    float r; asm("lg2.approx.f32 %0, %1;" : "=f"(r) : "f"(x)); return r;
}
__device__ __forceinline__ float lae2(float a, float b) {      // log2-add-exp2
    float m = fmaxf(a, b);
    return m + lg2(1.0f + ex2(-fabsf(a - b)));
}
__device__ __forceinline__ float lae3(float a, float b, float c) {
    float m = fmaxf(a, fmaxf(b, c));
    return m + lg2(ex2(a - m) + ex2(b - m) + ex2(c - m));
}

__device__ __forceinline__ void mbar_init(uint32_t a, uint32_t cnt) {
    asm volatile("mbarrier.init.shared.b64 [%0], %1;" :: "r"(a), "r"(cnt) : "memory");
}
__device__ __forceinline__ void mbar_arrive(uint32_t a) {
    asm volatile("mbarrier.arrive.shared.b64 _, [%0];" :: "r"(a) : "memory");
}
__device__ __forceinline__ void mbar_wait(uint32_t a, uint32_t parity) {
    asm volatile(
        "{\n\t.reg .pred P;\n\t"
        "LW_%=:\n\t"
        "mbarrier.try_wait.parity.acquire.cta.shared::cta.b64 P, [%0], %1, 0x989680;\n\t"
        "@!P bra LW_%=;\n\t}"
        :: "r"(a), "r"(parity) : "memory");
}

__global__ __launch_bounds__(64) void ctc_pc_kernel(
    const int* __restrict__ yt, const float* __restrict__ yp,
    float* __restrict__ out)
{
    const unsigned FULL = 0xffffffffu;
    __shared__ float ring[DSLOT][SLOTW];
    __shared__ __align__(8) unsigned long long mb[4]; // full0 full1 empty0 empty1

    const int tid = threadIdx.x;
    const int wid = tid >> 5;
    const int l = tid & 31;
    const int b = blockIdx.x;
    const float* __restrict__ rowf = yp + (size_t)b * TN * CN;
    const uint32_t mbase = (uint32_t)__cvta_generic_to_shared(mb);

    if (tid == 0) {
        mbar_init(mbase + 0, 32);   // full0
        mbar_init(mbase + 8, 32);   // full1
        mbar_init(mbase + 16, 32);  // empty0
        mbar_init(mbase + 24, 32);  // empty1
    }
    __syncthreads();

    const int lab = yt[b * LN + l];

    if (wid == 1) {
        // ---------------- producer ----------------
        const float4* __restrict__ row4 = (const float4*)rowf;
        float4 rg[4];
        #pragma unroll
        for (int i = 0; i < 4; ++i) rg[i] = row4[i * 32 + l];

        int pphase = 1;  // flipped so first empty-waits pass immediately
        for (int g = 0; g < NGRP; ++g) {
            const int st = g & 1;
            mbar_wait(mbase + 16 + 8 * st, (uint32_t)pphase);
            #pragma unroll
            for (int i = 0; i < GRP; ++i) {
                const int t = g * GRP + i;
                float4 v = rg[t & 3];
                const int tl = (t + 4 < TN) ? (t + 4) : (TN - 1);
                rg[t & 3] = row4[tl * 32 + l];

                float x0 = v.x * LOG2E, x1 = v.y * LOG2E,
                      x2 = v.z * LOG2E, x3 = v.w * LOG2E;
                float s = ex2(x0) + ex2(x1) + ex2(x2) + ex2(x3);
                #pragma unroll
                for (int o = 16; o; o >>= 1) s += __shfl_xor_sync(FULL, s, o);
                const float logZ = lg2(s);
                const float gb = __shfl_sync(FULL, x0, 0);          // blank (class 0)
                const float gl = __ldg(rowf + t * CN + lab) * LOG2E; // L1-hit gather

                ring[t & (DSLOT - 1)][l] = gl - logZ;
                if (l == 0) ring[t & (DSLOT - 1)][32] = gb - logZ;
            }
            mbar_arrive(mbase + 8 * st);     // full[st], all 32 lanes
            if (st) pphase ^= 1;
        }
    } else {
        // ---------------- consumer (alpha DP) ----------------
        const int labp = __shfl_up_sync(FULL, lab, 1);
        const bool skip = (l >= 1) && (lab != labp);
        const unsigned m = __ballot_sync(FULL, lab != PADV);
        const int len = __popc(m);

        // pre-seed so the t=0 update reproduces alpha0 exactly
        float a0 = 0.0f, a_odd = NEGF, a_even = NEGF;

        int cphase = 0;
        for (int g = 0; g < NGRP; ++g) {
            const int st = g & 1;
            mbar_wait(mbase + 8 * st, (uint32_t)cphase);
            #pragma unroll
            for (int i = 0; i < GRP; ++i) {
                const int t = g * GRP + i;
                const float lpl = ring[t & (DSLOT - 1)][l];
                const float lpb = ring[t & (DSLOT - 1)][32];

                float po = __shfl_up_sync(FULL, a_odd, 1);   // alpha[2l-1]
                float pe = __shfl_up_sync(FULL, a_even, 1);  // alpha[2l]
                po = (l == 0) ? NEGF : po;
                pe = (l == 0) ? a0 : pe;
                const float n_odd  = lpl + lae3(a_odd, pe, skip ? po : NEGF);
                const float n_even = lpb + lae2(a_even, a_odd);
                a0 += lpb;
                a_odd = n_odd; a_even = n_even;
            }
            mbar_arrive(mbase + 16 + 8 * st);  // empty[st]
            if (st) cphase ^= 1;
        }

        // loglik ends at states 2*len (even, lane len-1) and 2*len-1 (odd)
        const float ve = __shfl_sync(FULL, a_even, (len - 1) & 31);
        const float vo = __shfl_sync(FULL, a_odd, (len - 1) & 31);
        if (l == 0) {
            const float ll2 = (len >= 1) ? lae2(ve, vo) : a0;
            out[b] = -ll2 * NLN2;
        }
    }
}

extern "C" void kernel_launch(void* const* d_in, const int* in_sizes, int n_in,
                              void* d_out, int out_size) {
    const int* y_true = (const int*)d_in[0];     // [1024, 32] int32
    const float* y_pred = (const float*)d_in[1]; // [1024, 256, 128] float32
    float* out = (float*)d_out;                  // [1024] float32
    const int B = in_sizes[0] / LN;              // 1024
    ctc_pc_kernel<<<B, 64>>>(y_true, y_pred, out);
}